// round 2
// baseline (speedup 1.0000x reference)
#include <cuda_runtime.h>
#include <math.h>

#define NNODES 100000
#define KNB 16
#define F1 128
#define F2 64

// Scratch (bss, no allocation)
__device__ float g_h1[NNODES * 64];
__device__ float g_x1[NNODES * 64];
__device__ float g_h2[NNODES * 64];
__device__ float g_sd1[NNODES];
__device__ float g_ss1[NNODES];
__device__ float g_sd2[NNODES];
__device__ float g_ss2[NNODES];

// ---------------------------------------------------------------------------
// GEMM h = x @ W  (KD = inner dim, 64 output cols), fused epilogue computing
// s_dst[i] = h[i] . a[0:64], s_src[i] = h[i] . a[64:128].
// Block: 256 threads, 32 rows x 64 cols; thread -> (row = tid/8, 8 cols).
// ---------------------------------------------------------------------------
template <int KD>
__global__ void __launch_bounds__(256) gemm_att_kernel(
    const float* __restrict__ x, const float* __restrict__ W,
    const float* __restrict__ a, float* __restrict__ h,
    float* __restrict__ sd, float* __restrict__ ss)
{
    __shared__ float Ws[KD * 64];
    __shared__ float xs[32 * KD];

    const int tid = threadIdx.x;
    const int rowbase = blockIdx.x * 32;

    #pragma unroll 4
    for (int i = tid; i < KD * 64; i += 256) Ws[i] = W[i];
    #pragma unroll 4
    for (int i = tid; i < 32 * KD; i += 256) xs[i] = x[(size_t)rowbase * KD + i];
    __syncthreads();

    const int r  = tid >> 3;
    const int c0 = (tid & 7) * 8;

    float acc[8];
    #pragma unroll
    for (int j = 0; j < 8; j++) acc[j] = 0.0f;

    #pragma unroll 8
    for (int k = 0; k < KD; k++) {
        const float xv = xs[r * KD + k];
        const float4 w0 = *reinterpret_cast<const float4*>(&Ws[k * 64 + c0]);
        const float4 w1 = *reinterpret_cast<const float4*>(&Ws[k * 64 + c0 + 4]);
        acc[0] = fmaf(xv, w0.x, acc[0]);
        acc[1] = fmaf(xv, w0.y, acc[1]);
        acc[2] = fmaf(xv, w0.z, acc[2]);
        acc[3] = fmaf(xv, w0.w, acc[3]);
        acc[4] = fmaf(xv, w1.x, acc[4]);
        acc[5] = fmaf(xv, w1.y, acc[5]);
        acc[6] = fmaf(xv, w1.z, acc[6]);
        acc[7] = fmaf(xv, w1.w, acc[7]);
    }

    // epilogue: partial attention dots
    float pd = 0.0f, ps = 0.0f;
    #pragma unroll
    for (int j = 0; j < 8; j++) {
        pd = fmaf(acc[j], a[c0 + j], pd);
        ps = fmaf(acc[j], a[64 + c0 + j], ps);
    }
    // reduce across the 8 threads sharing a row (aligned 8-lane groups)
    #pragma unroll
    for (int off = 4; off >= 1; off >>= 1) {
        pd += __shfl_xor_sync(0xffffffffu, pd, off);
        ps += __shfl_xor_sync(0xffffffffu, ps, off);
    }
    const int row = rowbase + r;
    if ((tid & 7) == 0) {
        sd[row] = pd;
        ss[row] = ps;
    }

    float4* hp = reinterpret_cast<float4*>(&h[(size_t)row * 64 + c0]);
    hp[0] = make_float4(acc[0], acc[1], acc[2], acc[3]);
    hp[1] = make_float4(acc[4], acc[5], acc[6], acc[7]);
}

// ---------------------------------------------------------------------------
// Per-node attention softmax (K=16) + gather-weighted aggregation + bias + relu
// One warp per node. Each lane owns 2 feature cols via float2.
// ---------------------------------------------------------------------------
__global__ void __launch_bounds__(256) agg_kernel(
    const float2* __restrict__ h, const int* __restrict__ ecol,
    const float* __restrict__ sd, const float* __restrict__ ss,
    const float* __restrict__ b, float2* __restrict__ out)
{
    const int gwarp = (blockIdx.x * blockDim.x + threadIdx.x) >> 5;
    const int lane  = threadIdx.x & 31;
    if (gwarp >= NNODES) return;

    int   col = 0;
    float att;
    if (lane < KNB) {
        col = ecol[gwarp * KNB + lane];
        float ev = sd[gwarp] + ss[col];
        ev = (ev > 0.0f) ? ev : 0.2f * ev;   // leaky_relu slope 0.2
        att = ev;
    } else {
        att = -1e30f;
    }

    // softmax over 16 lanes (offsets <= 8 keep halves independent)
    float m = att;
    #pragma unroll
    for (int off = 8; off >= 1; off >>= 1)
        m = fmaxf(m, __shfl_xor_sync(0xffffffffu, m, off));
    float ex = (lane < KNB) ? __expf(att - m) : 0.0f;
    float s = ex;
    #pragma unroll
    for (int off = 8; off >= 1; off >>= 1)
        s += __shfl_xor_sync(0xffffffffu, s, off);
    att = ex / s;   // valid in lanes 0..15

    float2 acc = make_float2(0.0f, 0.0f);
    #pragma unroll
    for (int k = 0; k < KNB; k++) {
        const int   ck = __shfl_sync(0xffffffffu, col, k);
        const float ak = __shfl_sync(0xffffffffu, att, k);
        const float2 hv = h[(size_t)ck * 32 + lane];
        acc.x = fmaf(ak, hv.x, acc.x);
        acc.y = fmaf(ak, hv.y, acc.y);
    }

    const float2 bv = reinterpret_cast<const float2*>(b)[lane];
    acc.x = fmaxf(acc.x + bv.x, 0.0f);
    acc.y = fmaxf(acc.y + bv.y, 0.0f);
    out[(size_t)gwarp * 32 + lane] = acc;
}

// ---------------------------------------------------------------------------
extern "C" void kernel_launch(void* const* d_in, const int* in_sizes, int n_in,
                              void* d_out, int out_size)
{
    const float* x    = (const float*)d_in[0];
    // d_in[1] = edge_row: exactly K per node, row-sorted -> implicit, unused
    const int*   ecol = (const int*)d_in[2];
    const float* W1   = (const float*)d_in[3];
    const float* a1   = (const float*)d_in[4];
    const float* b1   = (const float*)d_in[5];
    const float* W2   = (const float*)d_in[6];
    const float* a2   = (const float*)d_in[7];
    const float* b2   = (const float*)d_in[8];

    float *h1, *x1, *h2, *sd1, *ss1, *sd2, *ss2;
    cudaGetSymbolAddress((void**)&h1,  g_h1);
    cudaGetSymbolAddress((void**)&x1,  g_x1);
    cudaGetSymbolAddress((void**)&h2,  g_h2);
    cudaGetSymbolAddress((void**)&sd1, g_sd1);
    cudaGetSymbolAddress((void**)&ss1, g_ss1);
    cudaGetSymbolAddress((void**)&sd2, g_sd2);
    cudaGetSymbolAddress((void**)&ss2, g_ss2);

    const int gemm_blocks = NNODES / 32;       // 3125 (exact)
    const int agg_blocks  = NNODES / 8;        // 12500 warps-of-8 (exact)

    // Layer 1
    gemm_att_kernel<F1><<<gemm_blocks, 256>>>(x, W1, a1, h1, sd1, ss1);
    agg_kernel<<<agg_blocks, 256>>>((const float2*)h1, ecol, sd1, ss1, b1,
                                    (float2*)x1);
    // Layer 2
    gemm_att_kernel<F2><<<gemm_blocks, 256>>>(x1, W2, a2, h2, sd2, ss2);
    agg_kernel<<<agg_blocks, 256>>>((const float2*)h2, ecol, sd2, ss2, b2,
                                    (float2*)d_out);
}

// round 3
// speedup vs baseline: 1.7578x; 1.7578x over previous
#include <cuda_runtime.h>
#include <math.h>

#define NNODES 100000
#define KNB 16

// Scratch (bss, no allocation)
__device__ float g_h1[NNODES * 64];
__device__ float g_x1[NNODES * 64];
__device__ float g_h2[NNODES * 64];
__device__ float g_sd1[NNODES];
__device__ float g_ss1[NNODES];
__device__ float g_sd2[NNODES];
__device__ float g_ss2[NNODES];

// ---------------------------------------------------------------------------
// GEMM h = x @ W  (KD inner dim, 64 output cols) with fused attention-dot
// epilogue:  sd[i] = h[i].a[0:64],  ss[i] = h[i].a[64:128].
// Tile: 64 rows x 64 cols per block, 256 threads, 4x4 outputs per thread.
// Per k-iter per thread: 1 LDS.128 (W) + 4 LDS.32 (x, broadcast -> conflict
// free) + 16 FFMA  ->  FMA-pipe bound.
// ---------------------------------------------------------------------------
template <int KD>
__global__ void __launch_bounds__(256) gemm_att_kernel(
    const float* __restrict__ x, const float* __restrict__ W,
    const float* __restrict__ a, float* __restrict__ h,
    float* __restrict__ sd, float* __restrict__ ss)
{
    extern __shared__ float smem[];
    float* Ws = smem;              // KD x 64
    float* xs = smem + KD * 64;    // 64 x KD (row-major, no pad needed)

    const int tid = threadIdx.x;
    const int rowbase = blockIdx.x * 64;

    // Fill W tile (float4 vectorized)
    {
        const float4* Wg = reinterpret_cast<const float4*>(W);
        float4* Wv = reinterpret_cast<float4*>(Ws);
        #pragma unroll
        for (int i = tid; i < KD * 16; i += 256) Wv[i] = Wg[i];
    }
    // Fill x tile (float4 vectorized, zero-pad out-of-range rows)
    {
        const float4* xg = reinterpret_cast<const float4*>(x + (size_t)rowbase * KD);
        float4* xv = reinterpret_cast<float4*>(xs);
        const int tot = 64 * KD / 4;
        const int nvalid_rows = NNODES - rowbase;
        const int validv = (nvalid_rows >= 64) ? tot : nvalid_rows * (KD / 4);
        for (int i = tid; i < tot; i += 256)
            xv[i] = (i < validv) ? xg[i] : make_float4(0.f, 0.f, 0.f, 0.f);
    }
    __syncthreads();

    const int tx = tid & 15;       // col group: cols tx*4 .. tx*4+3
    const int ty = tid >> 4;       // row group: rows ty*4 .. ty*4+3

    float acc[4][4];
    #pragma unroll
    for (int i = 0; i < 4; i++)
        #pragma unroll
        for (int j = 0; j < 4; j++) acc[i][j] = 0.0f;

    const float* xrow0 = &xs[(ty * 4 + 0) * KD];
    const float* xrow1 = &xs[(ty * 4 + 1) * KD];
    const float* xrow2 = &xs[(ty * 4 + 2) * KD];
    const float* xrow3 = &xs[(ty * 4 + 3) * KD];

    #pragma unroll 8
    for (int k = 0; k < KD; k++) {
        const float4 bv = *reinterpret_cast<const float4*>(&Ws[k * 64 + tx * 4]);
        const float a0 = xrow0[k];
        const float a1 = xrow1[k];
        const float a2 = xrow2[k];
        const float a3 = xrow3[k];
        acc[0][0] = fmaf(a0, bv.x, acc[0][0]);
        acc[0][1] = fmaf(a0, bv.y, acc[0][1]);
        acc[0][2] = fmaf(a0, bv.z, acc[0][2]);
        acc[0][3] = fmaf(a0, bv.w, acc[0][3]);
        acc[1][0] = fmaf(a1, bv.x, acc[1][0]);
        acc[1][1] = fmaf(a1, bv.y, acc[1][1]);
        acc[1][2] = fmaf(a1, bv.z, acc[1][2]);
        acc[1][3] = fmaf(a1, bv.w, acc[1][3]);
        acc[2][0] = fmaf(a2, bv.x, acc[2][0]);
        acc[2][1] = fmaf(a2, bv.y, acc[2][1]);
        acc[2][2] = fmaf(a2, bv.z, acc[2][2]);
        acc[2][3] = fmaf(a2, bv.w, acc[2][3]);
        acc[3][0] = fmaf(a3, bv.x, acc[3][0]);
        acc[3][1] = fmaf(a3, bv.y, acc[3][1]);
        acc[3][2] = fmaf(a3, bv.z, acc[3][2]);
        acc[3][3] = fmaf(a3, bv.w, acc[3][3]);
    }

    // Epilogue: attention partial dots + 16-lane reduction + stores
    const float4 aa = *reinterpret_cast<const float4*>(&a[tx * 4]);
    const float4 ab = *reinterpret_cast<const float4*>(&a[64 + tx * 4]);

    #pragma unroll
    for (int i = 0; i < 4; i++) {
        const int row = rowbase + ty * 4 + i;
        float pd = acc[i][0] * aa.x + acc[i][1] * aa.y +
                   acc[i][2] * aa.z + acc[i][3] * aa.w;
        float ps = acc[i][0] * ab.x + acc[i][1] * ab.y +
                   acc[i][2] * ab.z + acc[i][3] * ab.w;
        // reduce across the 16 tx lanes (contiguous half-warp; xor<=8 stays in half)
        #pragma unroll
        for (int off = 8; off >= 1; off >>= 1) {
            pd += __shfl_xor_sync(0xffffffffu, pd, off);
            ps += __shfl_xor_sync(0xffffffffu, ps, off);
        }
        if (row < NNODES) {
            if (tx == 0) { sd[row] = pd; ss[row] = ps; }
            *reinterpret_cast<float4*>(&h[(size_t)row * 64 + tx * 4]) =
                make_float4(acc[i][0], acc[i][1], acc[i][2], acc[i][3]);
        }
    }
}

// ---------------------------------------------------------------------------
// Attention softmax (K=16) + gather aggregation + bias + relu.
// 2 nodes per warp: lanes 0-15 -> node 2w, lanes 16-31 -> node 2w+1.
// Each lane owns 4 feature cols (float4) -> 1 LDG.128 per neighbor per lane.
// ---------------------------------------------------------------------------
__global__ void __launch_bounds__(256) agg_kernel(
    const float4* __restrict__ h, const int* __restrict__ ecol,
    const float* __restrict__ sd, const float* __restrict__ ss,
    const float* __restrict__ b, float4* __restrict__ out)
{
    const int warp = (blockIdx.x * blockDim.x + threadIdx.x) >> 5;
    const int lane = threadIdx.x & 31;
    const int l16  = lane & 15;
    const int node = warp * 2 + (lane >> 4);

    // perfectly coalesced: ecol[node*16 + l16] == ecol[warp*32 + lane]
    const int col = ecol[warp * 32 + lane];

    float ev = sd[node] + ss[col];
    ev = (ev > 0.0f) ? ev : 0.2f * ev;           // leaky_relu slope 0.2

    // softmax over the 16 lanes of this half-warp
    float m = ev;
    #pragma unroll
    for (int off = 8; off >= 1; off >>= 1)
        m = fmaxf(m, __shfl_xor_sync(0xffffffffu, m, off));
    const float ex = __expf(ev - m);
    float s = ex;
    #pragma unroll
    for (int off = 8; off >= 1; off >>= 1)
        s += __shfl_xor_sync(0xffffffffu, s, off);
    const float att = ex / s;

    float4 acc = make_float4(0.f, 0.f, 0.f, 0.f);
    #pragma unroll
    for (int k = 0; k < KNB; k++) {
        const int   ck = __shfl_sync(0xffffffffu, col, k, 16);
        const float ak = __shfl_sync(0xffffffffu, att, k, 16);
        const float4 hv = h[(size_t)ck * 16 + l16];
        acc.x = fmaf(ak, hv.x, acc.x);
        acc.y = fmaf(ak, hv.y, acc.y);
        acc.z = fmaf(ak, hv.z, acc.z);
        acc.w = fmaf(ak, hv.w, acc.w);
    }

    const float4 bv = reinterpret_cast<const float4*>(b)[l16];
    acc.x = fmaxf(acc.x + bv.x, 0.0f);
    acc.y = fmaxf(acc.y + bv.y, 0.0f);
    acc.z = fmaxf(acc.z + bv.z, 0.0f);
    acc.w = fmaxf(acc.w + bv.w, 0.0f);
    out[(size_t)node * 16 + l16] = acc;
}

// ---------------------------------------------------------------------------
extern "C" void kernel_launch(void* const* d_in, const int* in_sizes, int n_in,
                              void* d_out, int out_size)
{
    const float* x    = (const float*)d_in[0];
    // d_in[1] = edge_row: exactly K per node, row-sorted -> implicit, unused
    const int*   ecol = (const int*)d_in[2];
    const float* W1   = (const float*)d_in[3];
    const float* a1   = (const float*)d_in[4];
    const float* b1   = (const float*)d_in[5];
    const float* W2   = (const float*)d_in[6];
    const float* a2   = (const float*)d_in[7];
    const float* b2   = (const float*)d_in[8];

    float *h1, *x1, *h2, *sd1, *ss1, *sd2, *ss2;
    cudaGetSymbolAddress((void**)&h1,  g_h1);
    cudaGetSymbolAddress((void**)&x1,  g_x1);
    cudaGetSymbolAddress((void**)&h2,  g_h2);
    cudaGetSymbolAddress((void**)&sd1, g_sd1);
    cudaGetSymbolAddress((void**)&ss1, g_ss1);
    cudaGetSymbolAddress((void**)&sd2, g_sd2);
    cudaGetSymbolAddress((void**)&ss2, g_ss2);

    const int smem1 = (128 * 64 + 64 * 128) * 4;   // 64 KB
    const int smem2 = (64 * 64 + 64 * 64) * 4;     // 32 KB
    cudaFuncSetAttribute(gemm_att_kernel<128>,
                         cudaFuncAttributeMaxDynamicSharedMemorySize, smem1);

    const int gemm_blocks = (NNODES + 63) / 64;    // 1563
    const int agg_blocks  = NNODES / 16;           // 6250 (8 warps x 2 nodes)

    // Layer 1
    gemm_att_kernel<128><<<gemm_blocks, 256, smem1>>>(x, W1, a1, h1, sd1, ss1);
    agg_kernel<<<agg_blocks, 256>>>((const float4*)h1, ecol, sd1, ss1, b1,
                                    (float4*)x1);
    // Layer 2
    gemm_att_kernel<64><<<gemm_blocks, 256, smem2>>>(x1, W2, a2, h2, sd2, ss2);
    agg_kernel<<<agg_blocks, 256>>>((const float4*)h2, ecol, sd2, ss2, b2,
                                    (float4*)d_out);
}

// round 4
// speedup vs baseline: 2.6228x; 1.4921x over previous
#include <cuda_runtime.h>
#include <cuda_fp16.h>
#include <math.h>

#define NNODES 100000
#define KNB 16

// Scratch (bss, no allocation). h reused by both layers (sequential stream).
__device__ __align__(16) __half g_h[NNODES * 64];
__device__ __align__(16) float  g_x1[NNODES * 64];
__device__ float g_sd[NNODES];
__device__ float g_ss[NNODES];

// ---- packed f32x2 helpers --------------------------------------------------
__device__ __forceinline__ unsigned long long pack2(float v) {
    unsigned long long r;
    asm("mov.b64 %0, {%1, %1};" : "=l"(r) : "f"(v));
    return r;
}
__device__ __forceinline__ void ffma2(unsigned long long& d,
                                      unsigned long long a,
                                      unsigned long long b) {
    asm("fma.rn.f32x2 %0, %1, %2, %0;" : "+l"(d) : "l"(a), "l"(b));
}
__device__ __forceinline__ float2 unpack2(unsigned long long v) {
    float2 f;
    asm("mov.b64 {%0, %1}, %2;" : "=f"(f.x), "=f"(f.y) : "l"(v));
    return f;
}

// ---------------------------------------------------------------------------
// GEMM h = x @ W (KD inner, 64 cols) + fused attention dots
//   sd[i] = h[i].a[0:64], ss[i] = h[i].a[64:128];  h stored as fp16.
// Tile 64x64, 256 threads, 4x4 outputs/thread held as 8 f32x2 accumulators
// (column pairs). Mainloop per k/thread: 1 LDS.128 (W) + 4 LDS.32 (x, bcast)
// + 4 ALU packs + 8 FFMA2  -> fma-pipe instr count halved vs scalar FFMA.
// ---------------------------------------------------------------------------
template <int KD>
__global__ void __launch_bounds__(256) gemm_att_kernel(
    const float* __restrict__ x, const float* __restrict__ W,
    const float* __restrict__ a, __half* __restrict__ h,
    float* __restrict__ sd, float* __restrict__ ss)
{
    extern __shared__ float smem[];
    float* Ws = smem;              // KD x 64
    float* xs = smem + KD * 64;    // 64 x KD row-major

    const int tid = threadIdx.x;
    const int rowbase = blockIdx.x * 64;

    {
        const float4* Wg = reinterpret_cast<const float4*>(W);
        float4* Wv = reinterpret_cast<float4*>(Ws);
        #pragma unroll
        for (int i = tid; i < KD * 16; i += 256) Wv[i] = Wg[i];
    }
    {
        const float4* xg = reinterpret_cast<const float4*>(x + (size_t)rowbase * KD);
        float4* xv = reinterpret_cast<float4*>(xs);
        const int tot = 64 * KD / 4;
        const int nvalid_rows = NNODES - rowbase;
        const int validv = (nvalid_rows >= 64) ? tot : nvalid_rows * (KD / 4);
        for (int i = tid; i < tot; i += 256)
            xv[i] = (i < validv) ? xg[i] : make_float4(0.f, 0.f, 0.f, 0.f);
    }
    __syncthreads();

    const int tx = tid & 15;       // cols tx*4 .. tx*4+3
    const int ty = tid >> 4;       // rows ty*4 .. ty*4+3

    unsigned long long acc[4][2];
    #pragma unroll
    for (int i = 0; i < 4; i++) { acc[i][0] = 0ull; acc[i][1] = 0ull; }

    const float* xrow0 = &xs[(ty * 4 + 0) * KD];
    const float* xrow1 = &xs[(ty * 4 + 1) * KD];
    const float* xrow2 = &xs[(ty * 4 + 2) * KD];
    const float* xrow3 = &xs[(ty * 4 + 3) * KD];

    #pragma unroll 8
    for (int k = 0; k < KD; k++) {
        const ulonglong2 w =
            *reinterpret_cast<const ulonglong2*>(&Ws[k * 64 + tx * 4]);
        const unsigned long long a0 = pack2(xrow0[k]);
        const unsigned long long a1 = pack2(xrow1[k]);
        const unsigned long long a2 = pack2(xrow2[k]);
        const unsigned long long a3 = pack2(xrow3[k]);
        ffma2(acc[0][0], a0, w.x); ffma2(acc[0][1], a0, w.y);
        ffma2(acc[1][0], a1, w.x); ffma2(acc[1][1], a1, w.y);
        ffma2(acc[2][0], a2, w.x); ffma2(acc[2][1], a2, w.y);
        ffma2(acc[3][0], a3, w.x); ffma2(acc[3][1], a3, w.y);
    }

    const float4 aa = *reinterpret_cast<const float4*>(&a[tx * 4]);
    const float4 ab = *reinterpret_cast<const float4*>(&a[64 + tx * 4]);

    #pragma unroll
    for (int i = 0; i < 4; i++) {
        const int row = rowbase + ty * 4 + i;
        const float2 c01 = unpack2(acc[i][0]);
        const float2 c23 = unpack2(acc[i][1]);
        float pd = c01.x * aa.x + c01.y * aa.y + c23.x * aa.z + c23.y * aa.w;
        float ps = c01.x * ab.x + c01.y * ab.y + c23.x * ab.z + c23.y * ab.w;
        #pragma unroll
        for (int off = 8; off >= 1; off >>= 1) {
            pd += __shfl_xor_sync(0xffffffffu, pd, off);
            ps += __shfl_xor_sync(0xffffffffu, ps, off);
        }
        if (row < NNODES) {
            if (tx == 0) { sd[row] = pd; ss[row] = ps; }
            const __half2 ha = __floats2half2_rn(c01.x, c01.y);
            const __half2 hb = __floats2half2_rn(c23.x, c23.y);
            uint2 uv;
            uv.x = *reinterpret_cast<const unsigned*>(&ha);
            uv.y = *reinterpret_cast<const unsigned*>(&hb);
            *reinterpret_cast<uint2*>(&h[(size_t)row * 64 + tx * 4]) = uv;
        }
    }
}

// ---------------------------------------------------------------------------
// Attention softmax (K=16) + fp16 gather aggregation + bias + relu.
// One warp per node; each lane owns 2 cols as half2 -> one 128B line per
// neighbor row per warp (LDG.32 x32 lanes).
// ---------------------------------------------------------------------------
__global__ void __launch_bounds__(256) agg_kernel(
    const __half2* __restrict__ hh, const int* __restrict__ ecol,
    const float* __restrict__ sd, const float* __restrict__ ss,
    const float* __restrict__ b, float2* __restrict__ out)
{
    const int node = (blockIdx.x * blockDim.x + threadIdx.x) >> 5;
    const int lane = threadIdx.x & 31;

    int   col = 0;
    float att;
    if (lane < KNB) {
        col = ecol[node * KNB + lane];
        float ev = sd[node] + ss[col];
        att = (ev > 0.0f) ? ev : 0.2f * ev;     // leaky_relu slope 0.2
    } else {
        att = -1e30f;
    }

    float m = att;
    #pragma unroll
    for (int off = 8; off >= 1; off >>= 1)
        m = fmaxf(m, __shfl_xor_sync(0xffffffffu, m, off));
    const float ex = (lane < KNB) ? __expf(att - m) : 0.0f;
    float s = ex;
    #pragma unroll
    for (int off = 8; off >= 1; off >>= 1)
        s += __shfl_xor_sync(0xffffffffu, s, off);
    att = ex / s;                                // valid in lanes 0..15

    float2 acc = make_float2(0.f, 0.f);
    #pragma unroll
    for (int k = 0; k < KNB; k++) {
        const int   ck = __shfl_sync(0xffffffffu, col, k);
        const float ak = __shfl_sync(0xffffffffu, att, k);
        const float2 hv = __half22float2(hh[(size_t)ck * 32 + lane]);
        acc.x = fmaf(ak, hv.x, acc.x);
        acc.y = fmaf(ak, hv.y, acc.y);
    }

    const float2 bv = reinterpret_cast<const float2*>(b)[lane];
    acc.x = fmaxf(acc.x + bv.x, 0.0f);
    acc.y = fmaxf(acc.y + bv.y, 0.0f);
    out[(size_t)node * 32 + lane] = acc;
}

// ---------------------------------------------------------------------------
extern "C" void kernel_launch(void* const* d_in, const int* in_sizes, int n_in,
                              void* d_out, int out_size)
{
    const float* x    = (const float*)d_in[0];
    // d_in[1] = edge_row: exactly K per node, row-sorted -> implicit, unused
    const int*   ecol = (const int*)d_in[2];
    const float* W1   = (const float*)d_in[3];
    const float* a1   = (const float*)d_in[4];
    const float* b1   = (const float*)d_in[5];
    const float* W2   = (const float*)d_in[6];
    const float* a2   = (const float*)d_in[7];
    const float* b2   = (const float*)d_in[8];

    __half* h;  float *x1, *sd, *ss;
    cudaGetSymbolAddress((void**)&h,  g_h);
    cudaGetSymbolAddress((void**)&x1, g_x1);
    cudaGetSymbolAddress((void**)&sd, g_sd);
    cudaGetSymbolAddress((void**)&ss, g_ss);

    const int smem1 = (128 * 64 + 64 * 128) * 4;   // 64 KB
    const int smem2 = (64 * 64 + 64 * 64) * 4;     // 32 KB
    cudaFuncSetAttribute(gemm_att_kernel<128>,
                         cudaFuncAttributeMaxDynamicSharedMemorySize, smem1);

    const int gemm_blocks = (NNODES + 63) / 64;    // 1563
    const int agg_blocks  = NNODES / 8;            // 12500 (8 warps/block)

    // Layer 1
    gemm_att_kernel<128><<<gemm_blocks, 256, smem1>>>(x, W1, a1, h, sd, ss);
    agg_kernel<<<agg_blocks, 256>>>((const __half2*)h, ecol, sd, ss, b1,
                                    (float2*)x1);
    // Layer 2
    gemm_att_kernel<64><<<gemm_blocks, 256, smem2>>>(x1, W2, a2, h, sd, ss);
    agg_kernel<<<agg_blocks, 256>>>((const __half2*)h, ecol, sd, ss, b2,
                                    (float2*)d_out);
}